// round 15
// baseline (speedup 1.0000x reference)
#include <cuda_runtime.h>
#include <cstdint>

// out[b, y, x] = in[b, y + dyi[b], x - dxi[b]] if in-bounds else 0
// B=1024, WIN=256, C=1, fp32.
//
// 256-bit (v8.f32) loads/stores, one warp per QUAD of rows: 4 front-batched
// LDG.256 per thread = 8KB contiguous read window per warp; 4 STG.256 =
// 8KB contiguous write. Misalignment via shfl_down + uniform 8-way select.

static constexpr int WIN = 256;

__device__ __forceinline__ void ld_v8(const float* p, float* r) {
    asm volatile("ld.global.nc.v8.f32 {%0,%1,%2,%3,%4,%5,%6,%7}, [%8];"
                 : "=f"(r[0]), "=f"(r[1]), "=f"(r[2]), "=f"(r[3]),
                   "=f"(r[4]), "=f"(r[5]), "=f"(r[6]), "=f"(r[7])
                 : "l"(p));
}

__device__ __forceinline__ void st_v8(float* p, const float* r) {
    asm volatile("st.global.v8.f32 [%0], {%1,%2,%3,%4,%5,%6,%7,%8};"
                 :: "l"(p),
                    "f"(r[0]), "f"(r[1]), "f"(r[2]), "f"(r[3]),
                    "f"(r[4]), "f"(r[5]), "f"(r[6]), "f"(r[7])
                 : "memory");
}

// uniform s8 select: o[i] = (s8+i<8) ? a[s8+i] : n[s8+i-8]
__device__ __forceinline__ void sel8(int s8, const float* a, const float* n, float* o) {
    switch (s8) {
    case 0:
        o[0]=a[0]; o[1]=a[1]; o[2]=a[2]; o[3]=a[3];
        o[4]=a[4]; o[5]=a[5]; o[6]=a[6]; o[7]=a[7];
        break;
    case 1:
        o[0]=a[1]; o[1]=a[2]; o[2]=a[3]; o[3]=a[4];
        o[4]=a[5]; o[5]=a[6]; o[6]=a[7]; o[7]=n[0];
        break;
    case 2:
        o[0]=a[2]; o[1]=a[3]; o[2]=a[4]; o[3]=a[5];
        o[4]=a[6]; o[5]=a[7]; o[6]=n[0]; o[7]=n[1];
        break;
    case 3:
        o[0]=a[3]; o[1]=a[4]; o[2]=a[5]; o[3]=a[6];
        o[4]=a[7]; o[5]=n[0]; o[6]=n[1]; o[7]=n[2];
        break;
    case 4:
        o[0]=a[4]; o[1]=a[5]; o[2]=a[6]; o[3]=a[7];
        o[4]=n[0]; o[5]=n[1]; o[6]=n[2]; o[7]=n[3];
        break;
    case 5:
        o[0]=a[5]; o[1]=a[6]; o[2]=a[7]; o[3]=n[0];
        o[4]=n[1]; o[5]=n[2]; o[6]=n[3]; o[7]=n[4];
        break;
    case 6:
        o[0]=a[6]; o[1]=a[7]; o[2]=n[0]; o[3]=n[1];
        o[4]=n[2]; o[5]=n[3]; o[6]=n[4]; o[7]=n[5];
        break;
    default:
        o[0]=a[7]; o[1]=n[0]; o[2]=n[1]; o[3]=n[2];
        o[4]=n[3]; o[5]=n[4]; o[6]=n[5]; o[7]=n[6];
        break;
    }
}

__device__ __forceinline__ void emit_row_v8(
    const float* A, int s8, int w, int lane,
    const float* __restrict__ src, bool rowok, int sx0, float* dst)
{
    // neighbor's window (lane 31 loads its own, predicated)
    float N[8];
    #pragma unroll
    for (int i = 0; i < 8; i++)
        N[i] = __shfl_down_sync(0xffffffffu, A[i], 1);
    if (lane == 31 && rowok && (unsigned)(w + 1) < 32u)
        ld_v8(src + ((w + 1) << 3), N);

    float o[8];
    sel8(s8, A, N, o);

    unsigned base = rowok ? (unsigned)sx0 : 0xC0000000u;
    #pragma unroll
    for (int i = 0; i < 8; i++)
        if (base + (unsigned)i >= (unsigned)WIN) o[i] = 0.f;

    st_v8(dst, o);
}

__global__ __launch_bounds__(256, 3) void translation_kernel(
    const float* __restrict__ in,
    const float* __restrict__ dx,
    const float* __restrict__ dy,
    float* __restrict__ out)
{
    int idx  = blockIdx.x * blockDim.x + threadIdx.x;
    int lane = idx & 31;
    int quad = idx >> 5;              // row-quad index
    int b    = quad >> 6;             // 64 quads per batch
    int y0   = (quad & 63) << 2;      // first row of the quad

    int dxi = (int)dx[b];             // trunc toward zero == astype(int32)
    int dyi = (int)dy[b];

    int sy0 = y0 + dyi;
    bool ok0 = (unsigned)(sy0 + 0) < (unsigned)WIN;
    bool ok1 = (unsigned)(sy0 + 1) < (unsigned)WIN;
    bool ok2 = (unsigned)(sy0 + 2) < (unsigned)WIN;
    bool ok3 = (unsigned)(sy0 + 3) < (unsigned)WIN;

    const float* base = in + (b << 16);
    const float* src0 = base + ((ok0 ? sy0 + 0 : 0) << 8);
    const float* src1 = base + ((ok1 ? sy0 + 1 : 0) << 8);
    const float* src2 = base + ((ok2 ? sy0 + 2 : 0) << 8);
    const float* src3 = base + ((ok3 ? sy0 + 3 : 0) << 8);

    int sx0 = (lane << 3) - dxi;      // source index of first output float
    int w   = sx0 >> 3;               // aligned 8-float window
    int s8  = sx0 & 7;                // warp-uniform
    int wc  = w < 0 ? 0 : (w > 31 ? 31 : w);
    int woff = wc << 3;

    // 4 independent 256-bit loads up front (8KB contiguous window per warp)
    float A[8], B[8], C[8], D[8];
    ld_v8(src0 + woff, A);
    ld_v8(src1 + woff, B);
    ld_v8(src2 + woff, C);
    ld_v8(src3 + woff, D);

    float* dst = out + (((b << 8) | y0) << 8) + (lane << 3);
    emit_row_v8(A, s8, w, lane, src0, ok0, sx0, dst);
    emit_row_v8(B, s8, w, lane, src1, ok1, sx0, dst + WIN);
    emit_row_v8(C, s8, w, lane, src2, ok2, sx0, dst + 2 * WIN);
    emit_row_v8(D, s8, w, lane, src3, ok3, sx0, dst + 3 * WIN);
}

extern "C" void kernel_launch(void* const* d_in, const int* in_sizes, int n_in,
                              void* d_out, int out_size)
{
    const float* in  = (const float*)d_in[0];
    const float* dx  = (const float*)d_in[1];
    const float* dy  = (const float*)d_in[2];
    float*       out = (float*)d_out;

    // warps = B*WIN/4 = 65536 ; threads = 2,097,152
    int threads = 256;
    int blocks  = (1024 * 64 * 32) / threads;   // 8192
    translation_kernel<<<blocks, threads>>>(in, dx, dy, out);
}

// round 16
// speedup vs baseline: 1.0204x; 1.0204x over previous
#include <cuda_runtime.h>
#include <cstdint>

// out[b, y, x] = in[b, y + dyi[b], x - dxi[b]] if in-bounds else 0
// B=1024, WIN=256, C=1, fp32.
//
// 256-bit (v8.f32) loads/stores, one warp per row pair (R14 structure),
// with __launch_bounds__(256,6): reg cap 40 -> 75% theoretical occupancy
// (R14 used cap 5 / occ 50%). Misalignment via shfl_down + uniform select.

static constexpr int WIN = 256;

__device__ __forceinline__ void ld_v8(const float* p, float* r) {
    asm volatile("ld.global.nc.v8.f32 {%0,%1,%2,%3,%4,%5,%6,%7}, [%8];"
                 : "=f"(r[0]), "=f"(r[1]), "=f"(r[2]), "=f"(r[3]),
                   "=f"(r[4]), "=f"(r[5]), "=f"(r[6]), "=f"(r[7])
                 : "l"(p));
}

__device__ __forceinline__ void st_v8(float* p, const float* r) {
    asm volatile("st.global.v8.f32 [%0], {%1,%2,%3,%4,%5,%6,%7,%8};"
                 :: "l"(p),
                    "f"(r[0]), "f"(r[1]), "f"(r[2]), "f"(r[3]),
                    "f"(r[4]), "f"(r[5]), "f"(r[6]), "f"(r[7])
                 : "memory");
}

// uniform s8 select: o[i] = (s8+i<8) ? a[s8+i] : n[s8+i-8]
__device__ __forceinline__ void sel8(int s8, const float* a, const float* n, float* o) {
    switch (s8) {
    case 0:
        o[0]=a[0]; o[1]=a[1]; o[2]=a[2]; o[3]=a[3];
        o[4]=a[4]; o[5]=a[5]; o[6]=a[6]; o[7]=a[7];
        break;
    case 1:
        o[0]=a[1]; o[1]=a[2]; o[2]=a[3]; o[3]=a[4];
        o[4]=a[5]; o[5]=a[6]; o[6]=a[7]; o[7]=n[0];
        break;
    case 2:
        o[0]=a[2]; o[1]=a[3]; o[2]=a[4]; o[3]=a[5];
        o[4]=a[6]; o[5]=a[7]; o[6]=n[0]; o[7]=n[1];
        break;
    case 3:
        o[0]=a[3]; o[1]=a[4]; o[2]=a[5]; o[3]=a[6];
        o[4]=a[7]; o[5]=n[0]; o[6]=n[1]; o[7]=n[2];
        break;
    case 4:
        o[0]=a[4]; o[1]=a[5]; o[2]=a[6]; o[3]=a[7];
        o[4]=n[0]; o[5]=n[1]; o[6]=n[2]; o[7]=n[3];
        break;
    case 5:
        o[0]=a[5]; o[1]=a[6]; o[2]=a[7]; o[3]=n[0];
        o[4]=n[1]; o[5]=n[2]; o[6]=n[3]; o[7]=n[4];
        break;
    case 6:
        o[0]=a[6]; o[1]=a[7]; o[2]=n[0]; o[3]=n[1];
        o[4]=n[2]; o[5]=n[3]; o[6]=n[4]; o[7]=n[5];
        break;
    default:
        o[0]=a[7]; o[1]=n[0]; o[2]=n[1]; o[3]=n[2];
        o[4]=n[3]; o[5]=n[4]; o[6]=n[5]; o[7]=n[6];
        break;
    }
}

__device__ __forceinline__ void emit_row_v8(
    const float* A, int s8, int w, int lane,
    const float* __restrict__ src, bool rowok, int sx0, float* dst)
{
    // neighbor's window (lane 31 loads its own, predicated)
    float N[8];
    #pragma unroll
    for (int i = 0; i < 8; i++)
        N[i] = __shfl_down_sync(0xffffffffu, A[i], 1);
    if (lane == 31 && rowok && (unsigned)(w + 1) < 32u)
        ld_v8(src + ((w + 1) << 3), N);

    float o[8];
    sel8(s8, A, N, o);

    unsigned base = rowok ? (unsigned)sx0 : 0xC0000000u;
    #pragma unroll
    for (int i = 0; i < 8; i++)
        if (base + (unsigned)i >= (unsigned)WIN) o[i] = 0.f;

    st_v8(dst, o);
}

__global__ __launch_bounds__(256, 6) void translation_kernel(
    const float* __restrict__ in,
    const float* __restrict__ dx,
    const float* __restrict__ dy,
    float* __restrict__ out)
{
    int idx  = blockIdx.x * blockDim.x + threadIdx.x;
    int lane = idx & 31;
    int pair = idx >> 5;              // row pair index
    int b    = pair >> 7;             // 128 pairs per batch
    int y0   = (pair & 127) << 1;

    int dxi = (int)dx[b];             // trunc toward zero == astype(int32)
    int dyi = (int)dy[b];

    int sy0 = y0 + dyi;
    int sy1 = sy0 + 1;
    bool ok0 = (unsigned)sy0 < (unsigned)WIN;
    bool ok1 = (unsigned)sy1 < (unsigned)WIN;

    const float* base = in + (b << 16);
    const float* src0 = base + ((ok0 ? sy0 : 0) << 8);
    const float* src1 = base + ((ok1 ? sy1 : 0) << 8);

    int sx0 = (lane << 3) - dxi;      // source index of first output float
    int w   = sx0 >> 3;               // aligned 8-float window
    int s8  = sx0 & 7;                // warp-uniform
    int wc  = w < 0 ? 0 : (w > 31 ? 31 : w);
    int woff = wc << 3;

    // 2 independent 256-bit loads up front
    float A[8], B[8];
    ld_v8(src0 + woff, A);
    ld_v8(src1 + woff, B);

    float* dst = out + (((b << 8) | y0) << 8) + (lane << 3);
    emit_row_v8(A, s8, w, lane, src0, ok0, sx0, dst);
    emit_row_v8(B, s8, w, lane, src1, ok1, sx0, dst + WIN);
}

extern "C" void kernel_launch(void* const* d_in, const int* in_sizes, int n_in,
                              void* d_out, int out_size)
{
    const float* in  = (const float*)d_in[0];
    const float* dx  = (const float*)d_in[1];
    const float* dy  = (const float*)d_in[2];
    float*       out = (float*)d_out;

    // warps = B*WIN/2 = 131072 ; threads = 4,194,304
    int threads = 256;
    int blocks  = (1024 * 128 * 32) / threads;   // 16384
    translation_kernel<<<blocks, threads>>>(in, dx, dy, out);
}